// round 1
// baseline (speedup 1.0000x reference)
#include <cuda_runtime.h>
#include <math.h>
#include <stdint.h>

#define Zd  128
#define Nd  256
#define Fd  2048
#define Bd  8192
#define OSTRIDE 129   // Z+1

// ---------------- device scratch (no allocations allowed) ----------------
__device__ float g_h1[4][Nd];
__device__ float g_win [Fd * Zd];
__device__ float g_wout[Fd * Zd];
__device__ float g_bias[Fd];
__device__ float g_gate[Fd];
__device__ float g_gs  [Fd];   // gate[f] * s[f]

// ---------------- kernel 1: hypernet h0 -> h1 ----------------
// grid 4 (one block per k), block 256
__global__ void k_h1(const float* __restrict__ t,
                     const float* __restrict__ W1, const float* __restrict__ B1,
                     const float* __restrict__ W2, const float* __restrict__ B2) {
    __shared__ float h0[Nd];
    const int k = blockIdx.x;
    const int n = threadIdx.x;
    const float ts = t[0];
    h0[n] = tanhf(fmaf(W1[k * Nd + n], ts, B1[k * Nd + n]));
    __syncthreads();
    const float* __restrict__ w2 = W2 + (size_t)k * Nd * Nd + (size_t)n * Nd;
    float acc = B2[k * Nd + n];
#pragma unroll 8
    for (int m = 0; m < Nd; m++) acc = fmaf(w2[m], h0[m], acc);
    g_h1[k][n] = tanhf(acc);
}

// ---------------- kernel 2: w_in / w_out matvecs (HBM streaming) ----------------
// one warp per output row; grid covers 2*F*Z rows, 8 warps/block
__global__ void k_wproj(const float* __restrict__ W3_win,  const float* __restrict__ b3_win,
                        const float* __restrict__ W3_wout, const float* __restrict__ b3_wout) {
    __shared__ float h1a[Nd], h1b[Nd];
    const int t = threadIdx.x;
    h1a[t] = g_h1[0][t];
    h1b[t] = g_h1[1][t];
    __syncthreads();

    const int wid  = t >> 5;
    const int lane = t & 31;
    long r = (long)blockIdx.x * 8 + wid;

    const float* wmat; const float* bias; const float* hv; float* outp; long rr;
    if (r < (long)Fd * Zd) { rr = r;                 wmat = W3_win;  bias = b3_win;  hv = h1a; outp = g_win;  }
    else                   { rr = r - (long)Fd * Zd; wmat = W3_wout; bias = b3_wout; hv = h1b; outp = g_wout; }

    const float4* __restrict__ row = (const float4*)(wmat + rr * Nd);
    const float4* __restrict__ hv4 = (const float4*)hv;
    float acc = 0.f;
#pragma unroll
    for (int i = 0; i < 2; i++) {
        float4 v = row[lane + i * 32];
        float4 h = hv4[lane + i * 32];
        acc = fmaf(v.x, h.x, acc);
        acc = fmaf(v.y, h.y, acc);
        acc = fmaf(v.z, h.z, acc);
        acc = fmaf(v.w, h.w, acc);
    }
#pragma unroll
    for (int o = 16; o > 0; o >>= 1) acc += __shfl_xor_sync(0xFFFFFFFFu, acc, o);
    if (lane == 0) outp[rr] = acc + bias[rr];
}

// ---------------- kernel 3: bias, gate, gate*s ----------------
// grid 512, block 128 (4 warps = 4 f-rows per block)
__global__ void k_small(const float* __restrict__ W3_b,    const float* __restrict__ b3_b,
                        const float* __restrict__ W3_gate, const float* __restrict__ b3_gate) {
    __shared__ float h2[Nd], h3[Nd];
    const int t = threadIdx.x;
    h2[t] = g_h1[2][t];  h2[t + 128] = g_h1[2][t + 128];
    h3[t] = g_h1[3][t];  h3[t + 128] = g_h1[3][t + 128];
    __syncthreads();

    const int wid  = t >> 5;
    const int lane = t & 31;
    const int f = blockIdx.x * 4 + wid;

    const float4* rb = (const float4*)(W3_b    + (size_t)f * Nd);
    const float4* rg = (const float4*)(W3_gate + (size_t)f * Nd);
    const float4* h2v = (const float4*)h2;
    const float4* h3v = (const float4*)h3;

    float accb = 0.f, accg = 0.f;
#pragma unroll
    for (int i = 0; i < 2; i++) {
        float4 v = rb[lane + i * 32], h = h2v[lane + i * 32];
        accb = fmaf(v.x, h.x, fmaf(v.y, h.y, fmaf(v.z, h.z, fmaf(v.w, h.w, accb))));
        float4 v2 = rg[lane + i * 32], h4 = h3v[lane + i * 32];
        accg = fmaf(v2.x, h4.x, fmaf(v2.y, h4.y, fmaf(v2.z, h4.z, fmaf(v2.w, h4.w, accg))));
    }
    const float4 a  = ((const float4*)(g_win  + (size_t)f * Zd))[lane];
    const float4 b4 = ((const float4*)(g_wout + (size_t)f * Zd))[lane];
    float accs = a.x * b4.x + a.y * b4.y + a.z * b4.z + a.w * b4.w;

#pragma unroll
    for (int o = 16; o > 0; o >>= 1) {
        accb += __shfl_xor_sync(0xFFFFFFFFu, accb, o);
        accg += __shfl_xor_sync(0xFFFFFFFFu, accg, o);
        accs += __shfl_xor_sync(0xFFFFFFFFu, accs, o);
    }
    if (lane == 0) {
        g_bias[f] = accb + b3_b[f];
        float gt = 1.f / (1.f + expf(-(accg + b3_gate[f])));
        g_gate[f] = gt;
        g_gs[f]   = gt * accs;
    }
}

// ---------------- kernel 4: fused double GEMM + trace ----------------
// block: 256 threads handles BM=64 batch rows x all Z=128 output cols,
// looping F in tiles of BF=64. grid = 8192/64 = 128.
#define BM   64
#define BF   64
#define PADS 68   // padded row stride (floats) for transposed tiles; 16B-aligned rows

#define SMEM_FLOATS (Zd*PADS /*zs*/ + Zd*PADS /*ws*/ + BF*Zd /*wo*/ + BM*PADS /*gsm*/ + BM*17 /*trb*/)
#define SMEM_BYTES  (SMEM_FLOATS * 4)

__global__ __launch_bounds__(256, 1)
void k_main(const float* __restrict__ zlp, float* __restrict__ out) {
    extern __shared__ float sm[];
    float* zs  = sm;                    // [Zd][PADS]  zs[k][m]   (z transposed)
    float* ws  = zs  + Zd * PADS;       // [Zd][PADS]  ws[k][fi]  (w_in tile transposed)
    float* wo  = ws  + Zd * PADS;       // [BF][Zd]    w_out tile natural
    float* gsm = wo  + BF * Zd;         // [BM][PADS]  g tile
    float* trb = gsm + BM * PADS;       // [BM][17]

    const int t  = threadIdx.x;
    const int b0 = blockIdx.x * BM;

    // GEMM1 mapping: 16x16 thread grid, microtile 4 rows x 4 f
    const int tx = t & 15;   // f group
    const int ty = t >> 4;   // row group
    // GEMM2 mapping: 8x32 thread grid, microtile 8 rows x 4 zo
    const int cg = t & 31;
    const int rg = t >> 5;

    // load z tile transposed (once; reused over all f tiles)
#pragma unroll
    for (int i = 0; i < (BM * Zd) / 256; i++) {
        int idx = t + i * 256;
        int m = idx >> 7, k = idx & 127;
        zs[k * PADS + m] = zlp[(size_t)(b0 + m) * OSTRIDE + k];
    }

    float dz[8][4];
#pragma unroll
    for (int i = 0; i < 8; i++)
#pragma unroll
        for (int j = 0; j < 4; j++) dz[i][j] = 0.f;
    float tracc[4] = {0.f, 0.f, 0.f, 0.f};

    for (int f0 = 0; f0 < Fd; f0 += BF) {
        __syncthreads();   // previous GEMM2 done with ws/wo/gsm
        // load w_in tile transposed
#pragma unroll
        for (int i = 0; i < (BF * Zd) / 256; i++) {
            int idx = t + i * 256;
            int fi = idx >> 7, k = idx & 127;
            ws[k * PADS + fi] = g_win[(size_t)(f0 + fi) * Zd + k];
        }
        // load w_out tile (natural layout, float4)
        {
            const float4* src = (const float4*)(g_wout + (size_t)f0 * Zd);
            float4* dst = (float4*)wo;
#pragma unroll
            for (int i = 0; i < (BF * Zd / 4) / 256; i++) dst[t + i * 256] = src[t + i * 256];
        }
        __syncthreads();

        // ---- GEMM1: h tile (64x64) ----
        float acc[4][4];
#pragma unroll
        for (int i = 0; i < 4; i++)
#pragma unroll
            for (int j = 0; j < 4; j++) acc[i][j] = 0.f;

        const float* zp = zs + ty * 4;
        const float* wp = ws + tx * 4;
#pragma unroll 8
        for (int k = 0; k < Zd; k++) {
            float4 a = *(const float4*)(zp + k * PADS);
            float4 b = *(const float4*)(wp + k * PADS);
            float av[4] = {a.x, a.y, a.z, a.w};
            float bv[4] = {b.x, b.y, b.z, b.w};
#pragma unroll
            for (int i = 0; i < 4; i++)
#pragma unroll
                for (int j = 0; j < 4; j++)
                    acc[i][j] = fmaf(av[i], bv[j], acc[i][j]);
        }

        // epilogue: tanh, gate, trace, stage g to smem
#pragma unroll
        for (int j = 0; j < 4; j++) {
            int f = f0 + tx * 4 + j;
            float bias = g_bias[f];
            float gate = g_gate[f];
            float gs   = g_gs[f];
#pragma unroll
            for (int i = 0; i < 4; i++) {
                float h = tanhf(acc[i][j] + bias);
                float g = h * gate;
                tracc[i] = fmaf(1.f - h * h, gs, tracc[i]);
                gsm[(ty * 4 + i) * PADS + (tx * 4 + j)] = g;
            }
        }
        __syncthreads();

        // ---- GEMM2: dz += g_tile @ w_out_tile ----
        const float* grow = gsm + (rg * 8) * PADS;
#pragma unroll 2
        for (int fi = 0; fi < BF; fi++) {
            float4 w4 = *(const float4*)(wo + fi * Zd + cg * 4);
#pragma unroll
            for (int rr = 0; rr < 8; rr++) {
                float gv = grow[rr * PADS + fi];
                dz[rr][0] = fmaf(gv, w4.x, dz[rr][0]);
                dz[rr][1] = fmaf(gv, w4.y, dz[rr][1]);
                dz[rr][2] = fmaf(gv, w4.z, dz[rr][2]);
                dz[rr][3] = fmaf(gv, w4.w, dz[rr][3]);
            }
        }
    }

    // write dz_dt
    const float invF = 1.0f / (float)Fd;
#pragma unroll
    for (int rr = 0; rr < 8; rr++) {
        size_t base = (size_t)(b0 + rg * 8 + rr) * OSTRIDE + cg * 4;
        out[base + 0] = dz[rr][0] * invF;
        out[base + 1] = dz[rr][1] * invF;
        out[base + 2] = dz[rr][2] * invF;
        out[base + 3] = dz[rr][3] * invF;
    }

    // trace reduction (over the 16 tx groups)
    __syncthreads();
#pragma unroll
    for (int i = 0; i < 4; i++) trb[(ty * 4 + i) * 17 + tx] = tracc[i];
    __syncthreads();
    if (t < BM) {
        float s = 0.f;
#pragma unroll
        for (int x = 0; x < 16; x++) s += trb[t * 17 + x];
        out[(size_t)(b0 + t) * OSTRIDE + Zd] = -s * invF;
    }
}

// ---------------- launch ----------------
extern "C" void kernel_launch(void* const* d_in, const int* in_sizes, int n_in,
                              void* d_out, int out_size) {
    const float* t       = (const float*)d_in[0];
    const float* zlp     = (const float*)d_in[1];
    const float* W1      = (const float*)d_in[2];
    const float* B1      = (const float*)d_in[3];
    const float* W2      = (const float*)d_in[4];
    const float* B2      = (const float*)d_in[5];
    const float* W3_win  = (const float*)d_in[6];
    const float* b3_win  = (const float*)d_in[7];
    const float* W3_wout = (const float*)d_in[8];
    const float* b3_wout = (const float*)d_in[9];
    const float* W3_b    = (const float*)d_in[10];
    const float* b3_b    = (const float*)d_in[11];
    const float* W3_gate = (const float*)d_in[12];
    const float* b3_gate = (const float*)d_in[13];
    float* out = (float*)d_out;

    cudaFuncSetAttribute(k_main, cudaFuncAttributeMaxDynamicSharedMemorySize, SMEM_BYTES);

    k_h1   <<<4,     256>>>(t, W1, B1, W2, B2);
    k_wproj<<<65536, 256>>>(W3_win, b3_win, W3_wout, b3_wout);
    k_small<<<512,   128>>>(W3_b, b3_b, W3_gate, b3_gate);
    k_main <<<Bd / BM, 256, SMEM_BYTES>>>(zlp, out);
}